// round 2
// baseline (speedup 1.0000x reference)
#include <cuda_runtime.h>
#include <math.h>

// Problem constants
#define B_   2
#define H_   12
#define S_   2048
#define D_   128
#define BM   64      // query rows per CTA
#define BN   64      // keys per tile
#define KSTR 132     // smem row stride (floats) for Q/K/V tiles (128 + 4 pad)
#define PSTR 72      // smem row stride (floats) for P tiles (64 + 8 pad -> conflict-free)
#define NTH  256

static __device__ __forceinline__ float warp8_max(float x) {
    x = fmaxf(x, __shfl_xor_sync(0xffffffffu, x, 1));
    x = fmaxf(x, __shfl_xor_sync(0xffffffffu, x, 2));
    x = fmaxf(x, __shfl_xor_sync(0xffffffffu, x, 4));
    return x;
}
static __device__ __forceinline__ float warp8_sum(float x) {
    x += __shfl_xor_sync(0xffffffffu, x, 1);
    x += __shfl_xor_sync(0xffffffffu, x, 2);
    x += __shfl_xor_sync(0xffffffffu, x, 4);
    return x;
}

__global__ __launch_bounds__(NTH, 1)
void diffattn_kernel(const float* __restrict__ q1g, const float* __restrict__ k1g,
                     const float* __restrict__ vg,  const float* __restrict__ q2g,
                     const float* __restrict__ k2g, const float* __restrict__ lamg,
                     float* __restrict__ outg)
{
    extern __shared__ float sm[];
    float* q1s = sm;                      // BM*KSTR
    float* q2s = q1s + BM * KSTR;
    float* k1s = q2s + BM * KSTR;
    float* k2s = k1s + BN * KSTR;
    float* vs  = k2s + BN * KSTR;
    float* p1  = vs  + BN * KSTR;         // BM*PSTR
    float* p2  = p1  + BM * PSTR;

    const int bh  = blockIdx.y;
    const int bt  = (int)gridDim.x - 1 - (int)blockIdx.x;  // heavy tiles first
    const int tid = threadIdx.x;
    const int wid = tid >> 5;
    const int lane = tid & 31;
    const int grp = wid >> 2;       // 0 -> attention 1, 1 -> attention 2
    const int wim = wid & 3;        // warp within group
    const int rs  = lane >> 3;      // row sub-lane 0..3
    const int cs  = lane & 7;       // col sub-lane 0..7
    const int W   = wim * 16;       // warp row base within the 64-row tile

    const size_t base = (size_t)bh * S_ * D_;
    const int m0 = bt * BM;

    // ---- load both Q tiles (once) ----
    {
        const float4* g1 = (const float4*)(q1g + base + (size_t)m0 * D_);
        const float4* g2 = (const float4*)(q2g + base + (size_t)m0 * D_);
        for (int i = tid; i < BM * 32; i += NTH) {
            int r = i >> 5, c = i & 31;
            *((float4*)(q1s + r * KSTR) + c) = g1[(size_t)r * 32 + c];
            *((float4*)(q2s + r * KSTR) + c) = g2[(size_t)r * 32 + c];
        }
    }

    const float* qsm = grp ? q2s : q1s;
    const float* ksm = grp ? k2s : k1s;
    float*       ps  = grp ? p2  : p1;

    // accumulators: O[4 rows][4 d-chunks of float4] = 16 output floats per row set
    float4 o[4][4];
#pragma unroll
    for (int i = 0; i < 4; i++)
#pragma unroll
        for (int j = 0; j < 4; j++) o[i][j] = make_float4(0.f, 0.f, 0.f, 0.f);
    float mrow[4] = {-1e30f, -1e30f, -1e30f, -1e30f};
    float lrow[4] = {0.f, 0.f, 0.f, 0.f};

    const float scale = 0.08838834764831845f;   // 1/sqrt(128)

    for (int t = 0; t <= bt; ++t) {
        __syncthreads();   // previous tile's K/V/P fully consumed
        {
            const float4* gk1 = (const float4*)(k1g + base + (size_t)t * BN * D_);
            const float4* gk2 = (const float4*)(k2g + base + (size_t)t * BN * D_);
            const float4* gv  = (const float4*)(vg  + base + (size_t)t * BN * D_);
            for (int i = tid; i < BN * 32; i += NTH) {
                int r = i >> 5, c = i & 31;
                *((float4*)(k1s + r * KSTR) + c) = gk1[(size_t)r * 32 + c];
                *((float4*)(k2s + r * KSTR) + c) = gk2[(size_t)r * 32 + c];
                *((float4*)(vs  + r * KSTR) + c) = gv [(size_t)r * 32 + c];
            }
        }
        __syncthreads();

        // ---- QK^T: each lane computes 4 rows x 8 cols (interleaved ownership) ----
        float s[4][8];
#pragma unroll
        for (int i = 0; i < 4; i++)
#pragma unroll
            for (int j = 0; j < 8; j++) s[i][j] = 0.f;

#pragma unroll 4
        for (int d4 = 0; d4 < 32; ++d4) {
            float4 qv[4], kv[8];
#pragma unroll
            for (int i = 0; i < 4; i++)
                qv[i] = *((const float4*)(qsm + (W + rs + 4 * i) * KSTR) + d4);
#pragma unroll
            for (int j = 0; j < 8; j++)
                kv[j] = *((const float4*)(ksm + (cs + 8 * j) * KSTR) + d4);
#pragma unroll
            for (int i = 0; i < 4; i++)
#pragma unroll
                for (int j = 0; j < 8; j++) {
                    s[i][j] = fmaf(qv[i].x, kv[j].x, s[i][j]);
                    s[i][j] = fmaf(qv[i].y, kv[j].y, s[i][j]);
                    s[i][j] = fmaf(qv[i].z, kv[j].z, s[i][j]);
                    s[i][j] = fmaf(qv[i].w, kv[j].w, s[i][j]);
                }
        }

        // ---- scale + causal mask (only diagonal tile needs masking) ----
        if (t == bt) {
#pragma unroll
            for (int i = 0; i < 4; i++) {
                int m = m0 + W + rs + 4 * i;
#pragma unroll
                for (int j = 0; j < 8; j++) {
                    int n = t * BN + cs + 8 * j;
                    s[i][j] = (n > m) ? -1e30f : s[i][j] * scale;
                }
            }
        } else {
#pragma unroll
            for (int i = 0; i < 4; i++)
#pragma unroll
                for (int j = 0; j < 8; j++) s[i][j] *= scale;
        }

        // ---- online softmax + P store ----
#pragma unroll
        for (int i = 0; i < 4; i++) {
            float mx = s[i][0];
#pragma unroll
            for (int j = 1; j < 8; j++) mx = fmaxf(mx, s[i][j]);
            mx = warp8_max(mx);
            float mnew = fmaxf(mrow[i], mx);
            float corr = __expf(mrow[i] - mnew);
            mrow[i] = mnew;
            float sum = 0.f;
#pragma unroll
            for (int j = 0; j < 8; j++) { s[i][j] = __expf(s[i][j] - mnew); sum += s[i][j]; }
            sum = warp8_sum(sum);
            lrow[i] = lrow[i] * corr + sum;
#pragma unroll
            for (int jj = 0; jj < 4; jj++) {
                o[i][jj].x *= corr; o[i][jj].y *= corr;
                o[i][jj].z *= corr; o[i][jj].w *= corr;
            }
            float* pr = ps + (W + rs + 4 * i) * PSTR;
#pragma unroll
            for (int j = 0; j < 8; j++) pr[cs + 8 * j] = s[i][j];
        }
        __syncthreads();   // P visible to whole warp group

        // ---- P·V: each lane accumulates 4 rows x 16 d-cols ----
#pragma unroll 2
        for (int n = 0; n < BN; ++n) {
            float pv[4];
#pragma unroll
            for (int i = 0; i < 4; i++) pv[i] = ps[(W + rs + 4 * i) * PSTR + n];
            float4 vv[4];
#pragma unroll
            for (int jj = 0; jj < 4; jj++)
                vv[jj] = *((const float4*)(vs + n * KSTR) + (cs + 8 * jj));
#pragma unroll
            for (int i = 0; i < 4; i++)
#pragma unroll
                for (int jj = 0; jj < 4; jj++) {
                    o[i][jj].x = fmaf(pv[i], vv[jj].x, o[i][jj].x);
                    o[i][jj].y = fmaf(pv[i], vv[jj].y, o[i][jj].y);
                    o[i][jj].z = fmaf(pv[i], vv[jj].z, o[i][jj].z);
                    o[i][jj].w = fmaf(pv[i], vv[jj].w, o[i][jj].w);
                }
        }
    }

    // ---- epilogue: combine attn1 - lambda*attn2 via smem exchange ----
    __syncthreads();                 // all tile work done; k1s is dead -> reuse
    float lam = __expf(lamg[0]);
    float* xch = k1s;                // 64 rows x KSTR stride, holds lambda*O2/l2
    if (grp == 1) {
#pragma unroll
        for (int i = 0; i < 4; i++) {
            float f = lam / lrow[i];
            int r = W + rs + 4 * i;
#pragma unroll
            for (int jj = 0; jj < 4; jj++) {
                float4 a;
                a.x = o[i][jj].x * f; a.y = o[i][jj].y * f;
                a.z = o[i][jj].z * f; a.w = o[i][jj].w * f;
                *((float4*)(xch + r * KSTR) + (cs + 8 * jj)) = a;
            }
        }
    }
    __syncthreads();
    if (grp == 0) {
        float* og = outg + base + (size_t)m0 * D_;
#pragma unroll
        for (int i = 0; i < 4; i++) {
            float inv = 1.f / lrow[i];
            int r = W + rs + 4 * i;
#pragma unroll
            for (int jj = 0; jj < 4; jj++) {
                float4 b = *((const float4*)(xch + r * KSTR) + (cs + 8 * jj));
                float4 a;
                a.x = o[i][jj].x * inv - b.x;
                a.y = o[i][jj].y * inv - b.y;
                a.z = o[i][jj].z * inv - b.z;
                a.w = o[i][jj].w * inv - b.w;
                *((float4*)(og + (size_t)r * D_) + (cs + 8 * jj)) = a;
            }
        }
    }
}

extern "C" void kernel_launch(void* const* d_in, const int* in_sizes, int n_in,
                              void* d_out, int out_size)
{
    (void)in_sizes; (void)n_in; (void)out_size;
    const float* q1  = (const float*)d_in[0];
    const float* k1  = (const float*)d_in[1];
    const float* v   = (const float*)d_in[2];
    const float* q2  = (const float*)d_in[3];
    const float* k2  = (const float*)d_in[4];
    const float* lam = (const float*)d_in[5];
    float* out = (float*)d_out;

    const int smemBytes = (5 * 64 * KSTR + 2 * 64 * PSTR) * (int)sizeof(float); // 205824
    cudaFuncSetAttribute(diffattn_kernel,
                         cudaFuncAttributeMaxDynamicSharedMemorySize, smemBytes);

    dim3 grid(S_ / BM, B_ * H_);   // (32, 24)
    diffattn_kernel<<<grid, NTH, smemBytes>>>(q1, k1, v, q2, k2, lam, out);
}

// round 4
// speedup vs baseline: 1.1140x; 1.1140x over previous
#include <cuda_runtime.h>
#include <math.h>

// Problem constants
#define B_   2
#define H_   12
#define S_   2048
#define D_   128
#define BM   64      // query rows per CTA
#define BN   64      // keys per tile
#define KSTR 132     // smem row stride (floats) for Q/K/V tiles (128 + 4 pad)
#define PSTR 72      // smem row stride (floats) for P tiles (64 + 8 pad)
#define NTH  256

typedef unsigned long long u64;

// ---- packed fp32x2 helpers (sm_103a) ----
static __device__ __forceinline__ u64 fma2(u64 a, u64 b, u64 c) {
    u64 d;
    asm("fma.rn.f32x2 %0, %1, %2, %3;" : "=l"(d) : "l"(a), "l"(b), "l"(c));
    return d;
}
static __device__ __forceinline__ u64 mul2(u64 a, u64 b) {
    u64 d;
    asm("mul.rn.f32x2 %0, %1, %2;" : "=l"(d) : "l"(a), "l"(b));
    return d;
}
static __device__ __forceinline__ u64 splat2(float x) {
    u64 d;
    asm("mov.b64 %0, {%1, %1};" : "=l"(d) : "r"(__float_as_uint(x)));
    return d;
}
static __device__ __forceinline__ float2 unpack2(u64 v) {
    float2 r;
    asm("mov.b64 {%0, %1}, %2;" : "=f"(r.x), "=f"(r.y) : "l"(v));
    return r;
}

static __device__ __forceinline__ float warp8_max(float x) {
    x = fmaxf(x, __shfl_xor_sync(0xffffffffu, x, 1));
    x = fmaxf(x, __shfl_xor_sync(0xffffffffu, x, 2));
    x = fmaxf(x, __shfl_xor_sync(0xffffffffu, x, 4));
    return x;
}
static __device__ __forceinline__ float warp8_sum(float x) {
    x += __shfl_xor_sync(0xffffffffu, x, 1);
    x += __shfl_xor_sync(0xffffffffu, x, 2);
    x += __shfl_xor_sync(0xffffffffu, x, 4);
    return x;
}

__global__ __launch_bounds__(NTH, 1)
void diffattn_kernel(const float* __restrict__ q1g, const float* __restrict__ k1g,
                     const float* __restrict__ vg,  const float* __restrict__ q2g,
                     const float* __restrict__ k2g, const float* __restrict__ lamg,
                     float* __restrict__ outg)
{
    extern __shared__ float sm[];
    float* q1s = sm;                      // BM*KSTR
    float* q2s = q1s + BM * KSTR;
    float* k1s = q2s + BM * KSTR;
    float* k2s = k1s + BN * KSTR;
    float* vs  = k2s + BN * KSTR;
    float* p1  = vs  + BN * KSTR;         // BM*PSTR
    float* p2  = p1  + BM * PSTR;

    const int bh  = blockIdx.y;
    const int bt  = (int)gridDim.x - 1 - (int)blockIdx.x;  // heavy tiles first
    const int tid = threadIdx.x;
    const int wid = tid >> 5;
    const int lane = tid & 31;
    const int grp = wid >> 2;       // 0 -> attention 1, 1 -> attention 2
    const int wim = wid & 3;        // warp within group
    const int rs  = lane >> 3;      // row sub-lane 0..3
    const int cs  = lane & 7;       // col sub-lane 0..7
    const int W   = wim * 16;       // warp row base within the 64-row tile

    const size_t base = (size_t)bh * S_ * D_;
    const int m0 = bt * BM;

    // ---- load both Q tiles (once) ----
    {
        const float4* g1 = (const float4*)(q1g + base + (size_t)m0 * D_);
        const float4* g2 = (const float4*)(q2g + base + (size_t)m0 * D_);
        for (int i = tid; i < BM * 32; i += NTH) {
            int r = i >> 5, c = i & 31;
            *((float4*)(q1s + r * KSTR) + c) = g1[(size_t)r * 32 + c];
            *((float4*)(q2s + r * KSTR) + c) = g2[(size_t)r * 32 + c];
        }
    }

    const float* qsm = grp ? q2s : q1s;
    const float* ksm = grp ? k2s : k1s;
    float*       ps  = grp ? p2  : p1;

    // O accumulators: per row 16 d-floats = 8 f32x2 pairs
    u64 o2[4][8];
#pragma unroll
    for (int i = 0; i < 4; i++)
#pragma unroll
        for (int j = 0; j < 8; j++) o2[i][j] = 0ull;
    float mrow[4] = {-1e30f, -1e30f, -1e30f, -1e30f};
    float lrow[4] = {0.f, 0.f, 0.f, 0.f};

    const float scale = 0.08838834764831845f;   // 1/sqrt(128)

    for (int t = 0; t <= bt; ++t) {
        __syncthreads();   // previous tile's K/V/P fully consumed
        {
            const float4* gk1 = (const float4*)(k1g + base + (size_t)t * BN * D_);
            const float4* gk2 = (const float4*)(k2g + base + (size_t)t * BN * D_);
            const float4* gv  = (const float4*)(vg  + base + (size_t)t * BN * D_);
            for (int i = tid; i < BN * 32; i += NTH) {
                int r = i >> 5, c = i & 31;
                *((float4*)(k1s + r * KSTR) + c) = gk1[(size_t)r * 32 + c];
                *((float4*)(k2s + r * KSTR) + c) = gk2[(size_t)r * 32 + c];
                *((float4*)(vs  + r * KSTR) + c) = gv [(size_t)r * 32 + c];
            }
        }
        __syncthreads();

        // ---- QK^T with f32x2: accumulate pairs over d ----
        u64 acc[4][8];
#pragma unroll
        for (int i = 0; i < 4; i++)
#pragma unroll
            for (int j = 0; j < 8; j++) acc[i][j] = 0ull;

#pragma unroll 2
        for (int d4 = 0; d4 < 32; ++d4) {
            ulonglong2 qv[4];
#pragma unroll
            for (int i = 0; i < 4; i++)
                qv[i] = *((const ulonglong2*)(qsm + (W + rs + 4 * i) * KSTR) + d4);
#pragma unroll
            for (int jh = 0; jh < 2; ++jh) {
                ulonglong2 kv[4];
#pragma unroll
                for (int jj = 0; jj < 4; jj++)
                    kv[jj] = *((const ulonglong2*)(ksm + (cs + 8 * (4 * jh + jj)) * KSTR) + d4);
#pragma unroll
                for (int i = 0; i < 4; i++)
#pragma unroll
                    for (int jj = 0; jj < 4; jj++) {
                        int j = 4 * jh + jj;
                        acc[i][j] = fma2(qv[i].x, kv[jj].x, acc[i][j]);
                        acc[i][j] = fma2(qv[i].y, kv[jj].y, acc[i][j]);
                    }
            }
        }

        // horizontal reduce pairs -> scalar scores, scale + mask
        float s[4][8];
        if (t == bt) {
#pragma unroll
            for (int i = 0; i < 4; i++) {
                int m = m0 + W + rs + 4 * i;
#pragma unroll
                for (int j = 0; j < 8; j++) {
                    float2 h = unpack2(acc[i][j]);
                    int n = t * BN + cs + 8 * j;
                    s[i][j] = (n > m) ? -1e30f : (h.x + h.y) * scale;
                }
            }
        } else {
#pragma unroll
            for (int i = 0; i < 4; i++)
#pragma unroll
                for (int j = 0; j < 8; j++) {
                    float2 h = unpack2(acc[i][j]);
                    s[i][j] = (h.x + h.y) * scale;
                }
        }

        // ---- online softmax + P store ----
#pragma unroll
        for (int i = 0; i < 4; i++) {
            float mx = s[i][0];
#pragma unroll
            for (int j = 1; j < 8; j++) mx = fmaxf(mx, s[i][j]);
            mx = warp8_max(mx);
            float mnew = fmaxf(mrow[i], mx);
            float corr = __expf(mrow[i] - mnew);
            mrow[i] = mnew;
            float sum = 0.f;
#pragma unroll
            for (int j = 0; j < 8; j++) { s[i][j] = __expf(s[i][j] - mnew); sum += s[i][j]; }
            sum = warp8_sum(sum);
            lrow[i] = lrow[i] * corr + sum;
            u64 c2 = splat2(corr);
#pragma unroll
            for (int jj = 0; jj < 8; jj++) o2[i][jj] = mul2(o2[i][jj], c2);
            float* pr = ps + (W + rs + 4 * i) * PSTR;
#pragma unroll
            for (int j = 0; j < 8; j++) pr[cs + 8 * j] = s[i][j];
        }
        __syncthreads();   // P visible to whole warp group

        // ---- P·V with f32x2: o2 += splat(p) * vpair ----
#pragma unroll 2
        for (int n = 0; n < BN; n += 2) {
            float2 pp[4];
#pragma unroll
            for (int i = 0; i < 4; i++)
                pp[i] = *((const float2*)(ps + (W + rs + 4 * i) * PSTR + n));
#pragma unroll
            for (int nn = 0; nn < 2; ++nn) {
                ulonglong2 vv[4];
#pragma unroll
                for (int jj = 0; jj < 4; jj++)
                    vv[jj] = *((const ulonglong2*)(vs + (n + nn) * KSTR) + (cs + 8 * jj));
#pragma unroll
                for (int i = 0; i < 4; i++) {
                    u64 p2v = splat2(nn ? pp[i].y : pp[i].x);
#pragma unroll
                    for (int jj = 0; jj < 4; jj++) {
                        o2[i][2 * jj]     = fma2(p2v, vv[jj].x, o2[i][2 * jj]);
                        o2[i][2 * jj + 1] = fma2(p2v, vv[jj].y, o2[i][2 * jj + 1]);
                    }
                }
            }
        }
    }

    // ---- epilogue: combine attn1 - lambda*attn2 via smem exchange ----
    __syncthreads();                 // all tile work done; k1s is dead -> reuse
    float lam = __expf(lamg[0]);
    float* xch = k1s;                // 64 rows x KSTR stride, holds lambda*O2/l2
    if (grp == 1) {
#pragma unroll
        for (int i = 0; i < 4; i++) {
            u64 f2 = splat2(lam / lrow[i]);
            int r = W + rs + 4 * i;
#pragma unroll
            for (int jj = 0; jj < 4; jj++) {
                ulonglong2 a;
                a.x = mul2(o2[i][2 * jj], f2);
                a.y = mul2(o2[i][2 * jj + 1], f2);
                *((ulonglong2*)(xch + r * KSTR) + (cs + 8 * jj)) = a;
            }
        }
    }
    __syncthreads();
    if (grp == 0) {
        float* og = outg + base + (size_t)m0 * D_;
#pragma unroll
        for (int i = 0; i < 4; i++) {
            float inv = 1.f / lrow[i];
            int r = W + rs + 4 * i;
#pragma unroll
            for (int jj = 0; jj < 4; jj++) {
                ulonglong2 b = *((const ulonglong2*)(xch + r * KSTR) + (cs + 8 * jj));
                float2 b0 = unpack2(b.x), b1 = unpack2(b.y);
                float2 a0 = unpack2(o2[i][2 * jj]), a1 = unpack2(o2[i][2 * jj + 1]);
                float4 w;
                w.x = a0.x * inv - b0.x;
                w.y = a0.y * inv - b0.y;
                w.z = a1.x * inv - b1.x;
                w.w = a1.y * inv - b1.y;
                *((float4*)(og + (size_t)r * D_) + (cs + 8 * jj)) = w;
            }
        }
    }
}

extern "C" void kernel_launch(void* const* d_in, const int* in_sizes, int n_in,
                              void* d_out, int out_size)
{
    (void)in_sizes; (void)n_in; (void)out_size;
    const float* q1  = (const float*)d_in[0];
    const float* k1  = (const float*)d_in[1];
    const float* v   = (const float*)d_in[2];
    const float* q2  = (const float*)d_in[3];
    const float* k2  = (const float*)d_in[4];
    const float* lam = (const float*)d_in[5];
    float* out = (float*)d_out;

    const int smemBytes = (5 * 64 * KSTR + 2 * 64 * PSTR) * (int)sizeof(float); // 205824
    cudaFuncSetAttribute(diffattn_kernel,
                         cudaFuncAttributeMaxDynamicSharedMemorySize, smemBytes);

    dim3 grid(S_ / BM, B_ * H_);   // (32, 24)
    diffattn_kernel<<<grid, NTH, smemBytes>>>(q1, k1, v, q2, k2, lam, out);
}